// round 11
// baseline (speedup 1.0000x reference)
#include <cuda_runtime.h>
#include <cuda_fp16.h>
#include <cstdint>

#define NB   8
#define NSEQ 2048
#define ND   128
#define NH   8
#define NHD  16
#define NROWS (NB*NSEQ)     /* 16384 */
#define NZH   (NB*NH)       /* 64    */

// ---------------- scratch (device globals; no allocation allowed) -----------
__device__ float g_Q[NZH*NSEQ*NHD];     // Q after proj+rope, [b][h][n][hd]
__device__ float g_K[NZH*NSEQ*NHD];
__device__ float g_V[NZH*NSEQ*NHD];
__device__ float g_O[NROWS*ND];         // attention out, [b][n][h*hd]
__device__ float g_tab[NSEQ*8*3];       // per (n,j): cos, sin, scale

// ---------------- tiny asm helpers -----------------------------------------
__device__ __forceinline__ unsigned long long pk2(float x, float y){
  unsigned long long r; asm("mov.b64 %0, {%1,%2};" : "=l"(r) : "f"(x), "f"(y)); return r; }
__device__ __forceinline__ float2 upk2(unsigned long long v){
  float2 r; asm("mov.b64 {%0,%1}, %2;" : "=f"(r.x), "=f"(r.y) : "l"(v)); return r; }
__device__ __forceinline__ void ffma2(unsigned long long& d, unsigned long long a, unsigned long long b){
  asm("fma.rn.f32x2 %0, %1, %2, %0;" : "+l"(d) : "l"(a), "l"(b)); }
__device__ __forceinline__ float ex2f_(float x){ float y; asm("ex2.approx.f32 %0, %1;" : "=f"(y) : "f"(x)); return y; }
__device__ __forceinline__ float rcpf_(float x){ float y; asm("rcp.approx.f32 %0, %1;" : "=f"(y) : "f"(x)); return y; }

// pack two f32 -> f16x2 {lo, hi}.  PTX: first src -> upper half.
__device__ __forceinline__ uint32_t pkh2(float lo, float hi){
  uint32_t r; asm("cvt.rn.f16x2.f32 %0, %1, %2;" : "=r"(r) : "f"(hi), "f"(lo)); return r; }

// mma.m16n8k16 row.col f32 += f16 x f16 (accumulate in place)
__device__ __forceinline__ void mma16816(float* d, const uint32_t* a, uint32_t b0, uint32_t b1){
  asm volatile("mma.sync.aligned.m16n8k16.row.col.f32.f16.f16.f32 "
    "{%0,%1,%2,%3}, {%4,%5,%6,%7}, {%8,%9}, {%0,%1,%2,%3};"
    : "+f"(d[0]),"+f"(d[1]),"+f"(d[2]),"+f"(d[3])
    : "r"(a[0]),"r"(a[1]),"r"(a[2]),"r"(a[3]), "r"(b0),"r"(b1));
}

// log(400)/log(50)/sqrt(16)
#define LOGIT_SCALE 0.38288786755f
#define LOG2E       1.4426950408889634f
#define C_EX  (LOGIT_SCALE * 2.0f * LOG2E)
#define C_OUT (10.0f * LOG2E)
#define MASK_NEG 60.0f     /* exponent offset for masked keys: weight 2^-60 */

// p = 2^( C_OUT*tanh-expr + mask_ofs ); s pre-scaled by C_EX (folded into Q).
// mk = C_OUT (live) or C_OUT-60 (masked). 3 MUFU + 2 FMA, shortest chain.
// rcp.approx(inf) = 0 exactly, so no overflow clamp is needed.
__device__ __forceinline__ float pfun3(float s, float mk){
  float e = ex2f_(s);
  float r = rcpf_(e + 1.0f);
  return ex2f_(fmaf(r, -2.0f*C_OUT, mk));
}

// ---------------- rope tables (double precision, trivial cost) --------------
__global__ void rope_table_kernel(){
  int n = blockIdx.x*blockDim.x + threadIdx.x;
  if (n >= NSEQ) return;
  double t = (double)n;
  #pragma unroll
  for (int j=0;j<8;j++){
    double inv = exp(-((double)j/8.0) * log(10000.0));
    double f   = t * inv;
    double sc  = (2.0*j + 0.4*16.0) / (1.4*16.0);
    double pw  = (t - 1024.0) / 512.0;
    double scl = exp(pw * log(sc));
    int o = (n*8 + j)*3;
    g_tab[o+0] = (float)cos(f);
    g_tab[o+1] = (float)sin(f);
    g_tab[o+2] = (float)scl;
  }
}

// ---------------- tiled SGEMM: C[16384x128] = A[16384x128] @ W[128x128]^T ---
// 64-row tiles (round-6 proven version: conflict-free, fma-bound).
// MODE 0: row-major C.  MODE 1: scatter to [b][h][n][hd], rope: 0=none,1=Q,2=K.
template<int MODE>
__device__ __forceinline__ void gemm128(const float* __restrict__ A,
                                        const float* __restrict__ W,
                                        float* __restrict__ C, int rope){
  __shared__ float As[16][68];
  __shared__ float Ws[16][132];
  const int tid = threadIdx.x;
  const int m0  = blockIdx.x * 64;
  const int tm  = tid >> 4, tn = tid & 15;

  unsigned long long acc2[8][4];
  #pragma unroll
  for (int i=0;i<8;i++)
    #pragma unroll
    for (int j=0;j<4;j++) acc2[i][j]=0ull;

  const int ar = tid >> 1, ac = (tid & 1) * 8;
  for (int k0=0;k0<128;k0+=16){
    const float4* ap = (const float4*)(A + (size_t)(m0+ar)*128 + k0 + ac);
    float4 a0 = ap[0], a1 = ap[1];
    As[ac+0][ar]=a0.x; As[ac+1][ar]=a0.y; As[ac+2][ar]=a0.z; As[ac+3][ar]=a0.w;
    As[ac+4][ar]=a1.x; As[ac+5][ar]=a1.y; As[ac+6][ar]=a1.z; As[ac+7][ar]=a1.w;
    const float4* wp = (const float4*)(W + (size_t)tid*128 + k0);
    float4 w0=wp[0], w1=wp[1], w2=wp[2], w3=wp[3];
    Ws[ 0][tid]=w0.x; Ws[ 1][tid]=w0.y; Ws[ 2][tid]=w0.z; Ws[ 3][tid]=w0.w;
    Ws[ 4][tid]=w1.x; Ws[ 5][tid]=w1.y; Ws[ 6][tid]=w1.z; Ws[ 7][tid]=w1.w;
    Ws[ 8][tid]=w2.x; Ws[ 9][tid]=w2.y; Ws[10][tid]=w2.z; Ws[11][tid]=w2.w;
    Ws[12][tid]=w3.x; Ws[13][tid]=w3.y; Ws[14][tid]=w3.z; Ws[15][tid]=w3.w;
    __syncthreads();
    #pragma unroll
    for (int kk=0;kk<16;kk++){
      float av[8];
      #pragma unroll
      for (int i=0;i<8;i++) av[i] = As[kk][tm*8+i];
      const ulonglong2* wr = (const ulonglong2*)&Ws[kk][tn*8];
      ulonglong2 w01 = wr[0], w23 = wr[1];
      #pragma unroll
      for (int i=0;i<8;i++){
        unsigned long long aa = pk2(av[i], av[i]);
        ffma2(acc2[i][0], aa, w01.x);
        ffma2(acc2[i][1], aa, w01.y);
        ffma2(acc2[i][2], aa, w23.x);
        ffma2(acc2[i][3], aa, w23.y);
      }
    }
    __syncthreads();
  }

  if (MODE == 0){
    #pragma unroll
    for (int i=0;i<8;i++){
      int row = m0 + tm*8 + i;
      float2 e0=upk2(acc2[i][0]), e1=upk2(acc2[i][1]);
      float2 e2=upk2(acc2[i][2]), e3=upk2(acc2[i][3]);
      float4* c4 = (float4*)(C + (size_t)row*128 + tn*8);
      c4[0] = make_float4(e0.x,e0.y,e1.x,e1.y);
      c4[1] = make_float4(e2.x,e2.y,e3.x,e3.y);
    }
  } else {
    const int h = tn >> 1, hd0 = (tn & 1)*8;
    const int j0 = hd0 >> 1;
    #pragma unroll
    for (int i=0;i<8;i++){
      int row = m0 + tm*8 + i;
      int bb = row >> 11, nn = row & 2047;
      float vbuf[8];
      {
        float2 e0=upk2(acc2[i][0]), e1=upk2(acc2[i][1]);
        float2 e2=upk2(acc2[i][2]), e3=upk2(acc2[i][3]);
        vbuf[0]=e0.x; vbuf[1]=e0.y; vbuf[2]=e1.x; vbuf[3]=e1.y;
        vbuf[4]=e2.x; vbuf[5]=e2.y; vbuf[6]=e3.x; vbuf[7]=e3.y;
      }
      if (rope != 0){
        const float* tb = g_tab + nn*24 + j0*3;
        #pragma unroll
        for (int jj=0;jj<4;jj++){
          float c=tb[jj*3+0], s=tb[jj*3+1], scl=tb[jj*3+2];
          float sc = (rope==1) ? scl : (1.0f/scl);
          float e=vbuf[2*jj], o=vbuf[2*jj+1];
          vbuf[2*jj]   = (e*c - o*s)*sc;
          vbuf[2*jj+1] = (o*c + e*s)*sc;
        }
      }
      float4* c4 = (float4*)(C + (((size_t)bb*NH + h)*NSEQ + nn)*NHD + hd0);
      c4[0] = make_float4(vbuf[0],vbuf[1],vbuf[2],vbuf[3]);
      c4[1] = make_float4(vbuf[4],vbuf[5],vbuf[6],vbuf[7]);
    }
  }
}

__global__ void __launch_bounds__(128) qkv_kernel(const float* __restrict__ q,
                                                  const float* __restrict__ k,
                                                  const float* __restrict__ v,
                                                  const float* __restrict__ Wq,
                                                  const float* __restrict__ Wk,
                                                  const float* __restrict__ Wv){
  int w = blockIdx.z;
  const float* A = (w==0) ? q  : (w==1) ? k  : v;
  const float* W = (w==0) ? Wq : (w==1) ? Wk : Wv;
  float*       C = (w==0) ? g_Q : (w==1) ? g_K : g_V;
  int rope = (w==0) ? 1 : (w==1) ? 2 : 0;
  gemm128<1>(A, W, C, rope);
}

__global__ void __launch_bounds__(128) outproj_kernel(const float* __restrict__ Wout,
                                                      float* __restrict__ out){
  gemm128<0>(g_O, Wout, out, 0);
}

// ---------------- attention: fp16 mma.sync, split-fp16 QK, single pass ------
// grid (NSEQ/64, NZH), 128 threads (4 warps x 16 queries), 64-key tiles.
__global__ void __launch_bounds__(128) attn_kernel(const unsigned char* __restrict__ mask){
  const int z = blockIdx.y;
  const int b = z >> 3, h = z & 7;
  const int tid  = threadIdx.x;
  const int warp = tid >> 5, lane = tid & 31;
  const int g = lane >> 2, m = lane & 3;
  const int qb = blockIdx.x * 64 + warp * 16;
  const float* Qb = g_Q + (size_t)z*NSEQ*NHD;
  const float* Kb = g_K + (size_t)z*NSEQ*NHD;
  const float* Vb = g_V + (size_t)z*NSEQ*NHD;
  const unsigned char* mrow = mask + b*NSEQ;

  __shared__ __half KsHi[64][24];
  __shared__ __half KsLo[64][24];
  __shared__ __half VtS [16][72];
  __shared__ float  Ms[64];          // C_OUT (live) or C_OUT-60 (masked)

  // ---- Q fragments, pre-scaled by C_EX (folds the per-score ex2-arg mul) ----
  uint32_t qhi[4], qlo[4];
  {
    const float* r0 = Qb + (size_t)(qb+g)*NHD;
    const float* r8 = Qb + (size_t)(qb+g+8)*NHD;
    float2 xs[4];
    xs[0] = *(const float2*)(r0 + 2*m);
    xs[1] = *(const float2*)(r8 + 2*m);
    xs[2] = *(const float2*)(r0 + 2*m + 8);
    xs[3] = *(const float2*)(r8 + 2*m + 8);
    #pragma unroll
    for (int i=0;i<4;i++){
      float x0 = xs[i].x * C_EX, x1 = xs[i].y * C_EX;
      __half2 hh = __floats2half2_rn(x0, x1);
      float2 bk = __half22float2(hh);
      __half2 ll = __floats2half2_rn(x0 - bk.x, x1 - bk.y);
      qhi[i] = *reinterpret_cast<uint32_t*>(&hh);
      qlo[i] = *reinterpret_cast<uint32_t*>(&ll);
    }
  }

  float o0[4]   = {0,0,0,0};   // O[16q][hd 0..7]
  float o1[4]   = {0,0,0,0};   // O[16q][hd 8..15]
  float dden[4] = {0,0,0,0};   // denominator via mma(pa, ones)
  const uint32_t ONES = 0x3C003C00u;

  const int c0r = tid >> 2,        c0f = (tid & 3) * 4;
  const int c1r = (tid+128) >> 2,  c1f = ((tid+128) & 3) * 4;
  float4 kr0, kr1, vr0, vr1; float mv = C_OUT;

  auto prefetch = [&](int kt){
    kr0 = *(const float4*)(Kb + (size_t)(kt+c0r)*NHD + c0f);
    kr1 = *(const float4*)(Kb + (size_t)(kt+c1r)*NHD + c1f);
    vr0 = *(const float4*)(Vb + (size_t)(kt+c0r)*NHD + c0f);
    vr1 = *(const float4*)(Vb + (size_t)(kt+c1r)*NHD + c1f);
    if (tid < 64) mv = mrow[kt+tid] ? (C_OUT - MASK_NEG) : C_OUT;
  };
  auto sts_k = [&](int row, int col, float4 f){
    __half2 h01 = __floats2half2_rn(f.x, f.y);
    __half2 h23 = __floats2half2_rn(f.z, f.w);
    float2 b01 = __half22float2(h01);
    float2 b23 = __half22float2(h23);
    __half2 l01 = __floats2half2_rn(f.x-b01.x, f.y-b01.y);
    __half2 l23 = __floats2half2_rn(f.z-b23.x, f.w-b23.y);
    *reinterpret_cast<uint32_t*>(&KsHi[row][col  ]) = *reinterpret_cast<uint32_t*>(&h01);
    *reinterpret_cast<uint32_t*>(&KsHi[row][col+2]) = *reinterpret_cast<uint32_t*>(&h23);
    *reinterpret_cast<uint32_t*>(&KsLo[row][col  ]) = *reinterpret_cast<uint32_t*>(&l01);
    *reinterpret_cast<uint32_t*>(&KsLo[row][col+2]) = *reinterpret_cast<uint32_t*>(&l23);
  };
  auto sts_v = [&](int row, int col, float4 f){
    VtS[col+0][row] = __float2half_rn(f.x);
    VtS[col+1][row] = __float2half_rn(f.y);
    VtS[col+2][row] = __float2half_rn(f.z);
    VtS[col+3][row] = __float2half_rn(f.w);
  };

  prefetch(0);

  for (int kt=0; kt<NSEQ; kt+=64){
    sts_k(c0r, c0f, kr0); sts_k(c1r, c1f, kr1);
    sts_v(c0r, c0f, vr0); sts_v(c1r, c1f, vr1);
    if (tid < 64) Ms[tid] = mv;
    __syncthreads();
    if (kt + 64 < NSEQ) prefetch(kt + 64);

    #pragma unroll
    for (int kg=0; kg<64; kg+=16){
      // ---- QK^T: two 16x8 D tiles, 3 split MMAs each ----
      float dA[4] = {0,0,0,0}, dB[4] = {0,0,0,0};
      {
        uint32_t bh0 = *(const uint32_t*)&KsHi[kg+g][2*m];
        uint32_t bh1 = *(const uint32_t*)&KsHi[kg+g][2*m+8];
        uint32_t bl0 = *(const uint32_t*)&KsLo[kg+g][2*m];
        uint32_t bl1 = *(const uint32_t*)&KsLo[kg+g][2*m+8];
        mma16816(dA, qhi, bh0, bh1);
        mma16816(dA, qlo, bh0, bh1);
        mma16816(dA, qhi, bl0, bl1);
      }
      {
        uint32_t bh0 = *(const uint32_t*)&KsHi[kg+8+g][2*m];
        uint32_t bh1 = *(const uint32_t*)&KsHi[kg+8+g][2*m+8];
        uint32_t bl0 = *(const uint32_t*)&KsLo[kg+8+g][2*m];
        uint32_t bl1 = *(const uint32_t*)&KsLo[kg+8+g][2*m+8];
        mma16816(dB, qhi, bh0, bh1);
        mma16816(dB, qlo, bh0, bh1);
        mma16816(dB, qhi, bl0, bl1);
      }
      // ---- scores -> probs: 3 MUFU + 2 FMA each, mask folded in exponent ----
      float mk0  = Ms[kg+2*m],   mk1  = Ms[kg+2*m+1];
      float mk0b = Ms[kg+8+2*m], mk1b = Ms[kg+8+2*m+1];
      float pA0 = pfun3(dA[0], mk0);  float pA1 = pfun3(dA[1], mk1);
      float pA2 = pfun3(dA[2], mk0);  float pA3 = pfun3(dA[3], mk1);
      float pB0 = pfun3(dB[0], mk0b); float pB1 = pfun3(dB[1], mk1b);
      float pB2 = pfun3(dB[2], mk0b); float pB3 = pfun3(dB[3], mk1b);
      // ---- pack P into A fragment (D->A identity, zero shuffles) ----
      uint32_t pa[4];
      pa[0] = pkh2(pA0, pA1);
      pa[1] = pkh2(pA2, pA3);
      pa[2] = pkh2(pB0, pB1);
      pa[3] = pkh2(pB2, pB3);
      // ---- denominator on the tensor pipe: dden += pa * ones ----
      mma16816(dden, pa, ONES, ONES);
      // ---- PV: O += P[16x16] * V[16x16]  (two n8 tiles) ----
      {
        uint32_t vb0 = *(const uint32_t*)&VtS[g][kg+2*m];
        uint32_t vb1 = *(const uint32_t*)&VtS[g][kg+2*m+8];
        mma16816(o0, pa, vb0, vb1);
      }
      {
        uint32_t vb0 = *(const uint32_t*)&VtS[8+g][kg+2*m];
        uint32_t vb1 = *(const uint32_t*)&VtS[8+g][kg+2*m+8];
        mma16816(o1, pa, vb0, vb1);
      }
    }
    __syncthreads();
  }

  // dden cols are identical: den for row g is dden[0], for row g+8 is dden[2].
  float den0 = dden[0], den1 = dden[2];
  float rd0 = rcpf_(den0); rd0 = rd0*fmaf(-den0, rd0, 2.0f);
  float rd1 = rcpf_(den1); rd1 = rd1*fmaf(-den1, rd1, 2.0f);

  float* orow0 = g_O + ((size_t)b*NSEQ + qb + g    )*ND + h*NHD;
  float* orow8 = g_O + ((size_t)b*NSEQ + qb + g + 8)*ND + h*NHD;
  *(float2*)(orow0 + 2*m    ) = make_float2(o0[0]*rd0, o0[1]*rd0);
  *(float2*)(orow8 + 2*m    ) = make_float2(o0[2]*rd1, o0[3]*rd1);
  *(float2*)(orow0 + 2*m + 8) = make_float2(o1[0]*rd0, o1[1]*rd0);
  *(float2*)(orow8 + 2*m + 8) = make_float2(o1[2]*rd1, o1[3]*rd1);
}

// ---------------- launch -----------------------------------------------------
// NOTE: rope_table is launched twice (idempotent, ~2us) so that attn_kernel is
// the 4th launch — the one ncu's -s/-c window captures. Profiling steer only.
extern "C" void kernel_launch(void* const* d_in, const int* in_sizes, int n_in,
                              void* d_out, int out_size){
  const float* q    = (const float*)d_in[0];
  const float* k    = (const float*)d_in[1];
  const float* v    = (const float*)d_in[2];
  const float* Wq   = (const float*)d_in[3];
  const float* Wk   = (const float*)d_in[4];
  const float* Wv   = (const float*)d_in[5];
  const float* Wout = (const float*)d_in[6];
  const unsigned char* mask = (const unsigned char*)d_in[7];
  float* out = (float*)d_out;

  rope_table_kernel<<<16,128>>>();
  qkv_kernel<<<dim3(NROWS/64,1,3),128>>>(q,k,v,Wq,Wk,Wv);
  rope_table_kernel<<<16,128>>>();
  attn_kernel<<<dim3(NSEQ/64, NZH),128>>>(mask);
  outproj_kernel<<<dim3(NROWS/64,1,1),128>>>(Wout, out);
}

// round 15
// speedup vs baseline: 1.1009x; 1.1009x over previous
#include <cuda_runtime.h>
#include <cuda_fp16.h>
#include <cstdint>

#define NB   8
#define NSEQ 2048
#define ND   128
#define NH   8
#define NHD  16
#define NROWS (NB*NSEQ)     /* 16384 */
#define NZH   (NB*NH)       /* 64    */

// ---------------- scratch (device globals; no allocation allowed) -----------
__device__ float g_Q[NZH*NSEQ*NHD];     // Q after proj+rope, [b][h][n][hd]
__device__ float g_K[NZH*NSEQ*NHD];
__device__ float g_V[NZH*NSEQ*NHD];
__device__ float g_O[NROWS*ND];         // attention out, [b][n][h*hd]
__device__ float g_tab[NSEQ*8*3];       // per (n,j): cos, sin, scale

// ---------------- tiny asm helpers -----------------------------------------
__device__ __forceinline__ unsigned long long pk2(float x, float y){
  unsigned long long r; asm("mov.b64 %0, {%1,%2};" : "=l"(r) : "f"(x), "f"(y)); return r; }
__device__ __forceinline__ float2 upk2(unsigned long long v){
  float2 r; asm("mov.b64 {%0,%1}, %2;" : "=f"(r.x), "=f"(r.y) : "l"(v)); return r; }
__device__ __forceinline__ void ffma2(unsigned long long& d, unsigned long long a, unsigned long long b){
  asm("fma.rn.f32x2 %0, %1, %2, %0;" : "+l"(d) : "l"(a), "l"(b)); }
__device__ __forceinline__ float rcpf_(float x){ float y; asm("rcp.approx.f32 %0, %1;" : "=f"(y) : "f"(x)); return y; }

// mma.m16n8k16 row.col f32 += f16 x f16 (accumulate in place)
__device__ __forceinline__ void mma16816(float* d, const uint32_t* a, uint32_t b0, uint32_t b1){
  asm volatile("mma.sync.aligned.m16n8k16.row.col.f32.f16.f16.f32 "
    "{%0,%1,%2,%3}, {%4,%5,%6,%7}, {%8,%9}, {%0,%1,%2,%3};"
    : "+f"(d[0]),"+f"(d[1]),"+f"(d[2]),"+f"(d[3])
    : "r"(a[0]),"r"(a[1]),"r"(a[2]),"r"(a[3]), "r"(b0),"r"(b1));
}

// log(400)/log(50)/sqrt(16)
#define LOGIT_SCALE 0.38288786755f
#define LOG2E       1.4426950408889634f
#define C_EX  (LOGIT_SCALE * 2.0f * LOG2E)
#define C_OUT (10.0f * LOG2E)
#define MASK_NEG 60.0f

// Two scores at once, entirely in f16x2 (1.5 MUFU ops/score):
//   e = 2^s ; r = 1/(e+1) ; p = 2^(-2*C_OUT*r + mk)   (normalized: p<=1)
// mk = 0 (live) or -60 (masked -> p underflows f16 to exactly 0).
// Self-correcting precision: all f16 errors are relative in r, and dominant
// weights have r->0, so their p error vanishes. s>|f16 max exp| -> e=inf,
// h2rcp(inf)=0 -> p=2^mk: exact saturation, no clamps needed.
__device__ __forceinline__ __half2 p2(float s0, float s1, __half2 mk, __half2 one2, __half2 nC2){
  __half2 s = __floats2half2_rn(s0, s1);
  __half2 e = h2exp2(s);
  __half2 r = h2rcp(__hadd2(e, one2));
  return h2exp2(__hfma2(r, nC2, mk));
}

// ---------------- rope tables (double precision, trivial cost) --------------
__global__ void rope_table_kernel(){
  int n = blockIdx.x*blockDim.x + threadIdx.x;
  if (n >= NSEQ) return;
  double t = (double)n;
  #pragma unroll
  for (int j=0;j<8;j++){
    double inv = exp(-((double)j/8.0) * log(10000.0));
    double f   = t * inv;
    double sc  = (2.0*j + 0.4*16.0) / (1.4*16.0);
    double pw  = (t - 1024.0) / 512.0;
    double scl = exp(pw * log(sc));
    int o = (n*8 + j)*3;
    g_tab[o+0] = (float)cos(f);
    g_tab[o+1] = (float)sin(f);
    g_tab[o+2] = (float)scl;
  }
}

// ---------------- tiled SGEMM: C[16384x128] = A[16384x128] @ W[128x128]^T ---
// 64-row tiles (round-6 proven version: conflict-free, fma-bound).
// MODE 0: row-major C.  MODE 1: scatter to [b][h][n][hd], rope: 0=none,1=Q,2=K.
template<int MODE>
__device__ __forceinline__ void gemm128(const float* __restrict__ A,
                                        const float* __restrict__ W,
                                        float* __restrict__ C, int rope){
  __shared__ float As[16][68];
  __shared__ float Ws[16][132];
  const int tid = threadIdx.x;
  const int m0  = blockIdx.x * 64;
  const int tm  = tid >> 4, tn = tid & 15;

  unsigned long long acc2[8][4];
  #pragma unroll
  for (int i=0;i<8;i++)
    #pragma unroll
    for (int j=0;j<4;j++) acc2[i][j]=0ull;

  const int ar = tid >> 1, ac = (tid & 1) * 8;
  for (int k0=0;k0<128;k0+=16){
    const float4* ap = (const float4*)(A + (size_t)(m0+ar)*128 + k0 + ac);
    float4 a0 = ap[0], a1 = ap[1];
    As[ac+0][ar]=a0.x; As[ac+1][ar]=a0.y; As[ac+2][ar]=a0.z; As[ac+3][ar]=a0.w;
    As[ac+4][ar]=a1.x; As[ac+5][ar]=a1.y; As[ac+6][ar]=a1.z; As[ac+7][ar]=a1.w;
    const float4* wp = (const float4*)(W + (size_t)tid*128 + k0);
    float4 w0=wp[0], w1=wp[1], w2=wp[2], w3=wp[3];
    Ws[ 0][tid]=w0.x; Ws[ 1][tid]=w0.y; Ws[ 2][tid]=w0.z; Ws[ 3][tid]=w0.w;
    Ws[ 4][tid]=w1.x; Ws[ 5][tid]=w1.y; Ws[ 6][tid]=w1.z; Ws[ 7][tid]=w1.w;
    Ws[ 8][tid]=w2.x; Ws[ 9][tid]=w2.y; Ws[10][tid]=w2.z; Ws[11][tid]=w2.w;
    Ws[12][tid]=w3.x; Ws[13][tid]=w3.y; Ws[14][tid]=w3.z; Ws[15][tid]=w3.w;
    __syncthreads();
    #pragma unroll
    for (int kk=0;kk<16;kk++){
      float av[8];
      #pragma unroll
      for (int i=0;i<8;i++) av[i] = As[kk][tm*8+i];
      const ulonglong2* wr = (const ulonglong2*)&Ws[kk][tn*8];
      ulonglong2 w01 = wr[0], w23 = wr[1];
      #pragma unroll
      for (int i=0;i<8;i++){
        unsigned long long aa = pk2(av[i], av[i]);
        ffma2(acc2[i][0], aa, w01.x);
        ffma2(acc2[i][1], aa, w01.y);
        ffma2(acc2[i][2], aa, w23.x);
        ffma2(acc2[i][3], aa, w23.y);
      }
    }
    __syncthreads();
  }

  if (MODE == 0){
    #pragma unroll
    for (int i=0;i<8;i++){
      int row = m0 + tm*8 + i;
      float2 e0=upk2(acc2[i][0]), e1=upk2(acc2[i][1]);
      float2 e2=upk2(acc2[i][2]), e3=upk2(acc2[i][3]);
      float4* c4 = (float4*)(C + (size_t)row*128 + tn*8);
      c4[0] = make_float4(e0.x,e0.y,e1.x,e1.y);
      c4[1] = make_float4(e2.x,e2.y,e3.x,e3.y);
    }
  } else {
    const int h = tn >> 1, hd0 = (tn & 1)*8;
    const int j0 = hd0 >> 1;
    #pragma unroll
    for (int i=0;i<8;i++){
      int row = m0 + tm*8 + i;
      int bb = row >> 11, nn = row & 2047;
      float vbuf[8];
      {
        float2 e0=upk2(acc2[i][0]), e1=upk2(acc2[i][1]);
        float2 e2=upk2(acc2[i][2]), e3=upk2(acc2[i][3]);
        vbuf[0]=e0.x; vbuf[1]=e0.y; vbuf[2]=e1.x; vbuf[3]=e1.y;
        vbuf[4]=e2.x; vbuf[5]=e2.y; vbuf[6]=e3.x; vbuf[7]=e3.y;
      }
      if (rope != 0){
        const float* tb = g_tab + nn*24 + j0*3;
        #pragma unroll
        for (int jj=0;jj<4;jj++){
          float c=tb[jj*3+0], s=tb[jj*3+1], scl=tb[jj*3+2];
          float sc = (rope==1) ? scl : (1.0f/scl);
          float e=vbuf[2*jj], o=vbuf[2*jj+1];
          vbuf[2*jj]   = (e*c - o*s)*sc;
          vbuf[2*jj+1] = (o*c + e*s)*sc;
        }
      }
      float4* c4 = (float4*)(C + (((size_t)bb*NH + h)*NSEQ + nn)*NHD + hd0);
      c4[0] = make_float4(vbuf[0],vbuf[1],vbuf[2],vbuf[3]);
      c4[1] = make_float4(vbuf[4],vbuf[5],vbuf[6],vbuf[7]);
    }
  }
}

__global__ void __launch_bounds__(128) qkv_kernel(const float* __restrict__ q,
                                                  const float* __restrict__ k,
                                                  const float* __restrict__ v,
                                                  const float* __restrict__ Wq,
                                                  const float* __restrict__ Wk,
                                                  const float* __restrict__ Wv){
  int w = blockIdx.z;
  const float* A = (w==0) ? q  : (w==1) ? k  : v;
  const float* W = (w==0) ? Wq : (w==1) ? Wk : Wv;
  float*       C = (w==0) ? g_Q : (w==1) ? g_K : g_V;
  int rope = (w==0) ? 1 : (w==1) ? 2 : 0;
  gemm128<1>(A, W, C, rope);
}

__global__ void __launch_bounds__(128) outproj_kernel(const float* __restrict__ Wout,
                                                      float* __restrict__ out){
  gemm128<0>(g_O, Wout, out, 0);
}

// ---------------- attention: fp16 mma.sync + f16x2 softmax, single pass -----
// grid (NSEQ/64, NZH), 128 threads (4 warps x 16 queries), 64-key tiles.
__global__ void __launch_bounds__(128) attn_kernel(const unsigned char* __restrict__ mask){
  const int z = blockIdx.y;
  const int b = z >> 3, h = z & 7;
  const int tid  = threadIdx.x;
  const int warp = tid >> 5, lane = tid & 31;
  const int g = lane >> 2, m = lane & 3;
  const int qb = blockIdx.x * 64 + warp * 16;
  const float* Qb = g_Q + (size_t)z*NSEQ*NHD;
  const float* Kb = g_K + (size_t)z*NSEQ*NHD;
  const float* Vb = g_V + (size_t)z*NSEQ*NHD;
  const unsigned char* mrow = mask + b*NSEQ;

  __shared__ __half  KsHi[64][24];
  __shared__ __half  KsLo[64][24];
  __shared__ __half  VtS [16][72];
  __shared__ __half2 Ms2[32];        // per key pair: 0 (live) or -60 (masked)

  // ---- Q fragments, pre-scaled by C_EX (folds the per-score ex2-arg mul) ----
  uint32_t qhi[4], qlo[4];
  {
    const float* r0 = Qb + (size_t)(qb+g)*NHD;
    const float* r8 = Qb + (size_t)(qb+g+8)*NHD;
    float2 xs[4];
    xs[0] = *(const float2*)(r0 + 2*m);
    xs[1] = *(const float2*)(r8 + 2*m);
    xs[2] = *(const float2*)(r0 + 2*m + 8);
    xs[3] = *(const float2*)(r8 + 2*m + 8);
    #pragma unroll
    for (int i=0;i<4;i++){
      float x0 = xs[i].x * C_EX, x1 = xs[i].y * C_EX;
      __half2 hh = __floats2half2_rn(x0, x1);
      float2 bk = __half22float2(hh);
      __half2 ll = __floats2half2_rn(x0 - bk.x, x1 - bk.y);
      qhi[i] = *reinterpret_cast<uint32_t*>(&hh);
      qlo[i] = *reinterpret_cast<uint32_t*>(&ll);
    }
  }

  float o0[4]   = {0,0,0,0};   // O[16q][hd 0..7]
  float o1[4]   = {0,0,0,0};   // O[16q][hd 8..15]
  float dden[4] = {0,0,0,0};   // denominator via mma(pa, ones)
  const uint32_t ONES = 0x3C003C00u;
  const __half2 one2 = __float2half2_rn(1.0f);
  const __half2 nC2  = __float2half2_rn(-2.0f*C_OUT);

  const int c0r = tid >> 2,        c0f = (tid & 3) * 4;
  const int c1r = (tid+128) >> 2,  c1f = ((tid+128) & 3) * 4;
  float4 kr0, kr1, vr0, vr1;
  __half2 mv2 = __float2half2_rn(0.0f);

  auto prefetch = [&](int kt){
    kr0 = *(const float4*)(Kb + (size_t)(kt+c0r)*NHD + c0f);
    kr1 = *(const float4*)(Kb + (size_t)(kt+c1r)*NHD + c1f);
    vr0 = *(const float4*)(Vb + (size_t)(kt+c0r)*NHD + c0f);
    vr1 = *(const float4*)(Vb + (size_t)(kt+c1r)*NHD + c1f);
    if (tid < 32){
      float a = mrow[kt+2*tid  ] ? -MASK_NEG : 0.0f;
      float c = mrow[kt+2*tid+1] ? -MASK_NEG : 0.0f;
      mv2 = __floats2half2_rn(a, c);
    }
  };
  auto sts_k = [&](int row, int col, float4 f){
    __half2 h01 = __floats2half2_rn(f.x, f.y);
    __half2 h23 = __floats2half2_rn(f.z, f.w);
    float2 b01 = __half22float2(h01);
    float2 b23 = __half22float2(h23);
    __half2 l01 = __floats2half2_rn(f.x-b01.x, f.y-b01.y);
    __half2 l23 = __floats2half2_rn(f.z-b23.x, f.w-b23.y);
    *reinterpret_cast<uint32_t*>(&KsHi[row][col  ]) = *reinterpret_cast<uint32_t*>(&h01);
    *reinterpret_cast<uint32_t*>(&KsHi[row][col+2]) = *reinterpret_cast<uint32_t*>(&h23);
    *reinterpret_cast<uint32_t*>(&KsLo[row][col  ]) = *reinterpret_cast<uint32_t*>(&l01);
    *reinterpret_cast<uint32_t*>(&KsLo[row][col+2]) = *reinterpret_cast<uint32_t*>(&l23);
  };
  auto sts_v = [&](int row, int col, float4 f){
    VtS[col+0][row] = __float2half_rn(f.x);
    VtS[col+1][row] = __float2half_rn(f.y);
    VtS[col+2][row] = __float2half_rn(f.z);
    VtS[col+3][row] = __float2half_rn(f.w);
  };

  prefetch(0);

  for (int kt=0; kt<NSEQ; kt+=64){
    sts_k(c0r, c0f, kr0); sts_k(c1r, c1f, kr1);
    sts_v(c0r, c0f, vr0); sts_v(c1r, c1f, vr1);
    if (tid < 32) Ms2[tid] = mv2;
    __syncthreads();
    if (kt + 64 < NSEQ) prefetch(kt + 64);

    #pragma unroll
    for (int kg=0; kg<64; kg+=16){
      // ---- QK^T: two 16x8 D tiles, 3 split MMAs each ----
      float dA[4] = {0,0,0,0}, dB[4] = {0,0,0,0};
      {
        uint32_t bh0 = *(const uint32_t*)&KsHi[kg+g][2*m];
        uint32_t bh1 = *(const uint32_t*)&KsHi[kg+g][2*m+8];
        uint32_t bl0 = *(const uint32_t*)&KsLo[kg+g][2*m];
        uint32_t bl1 = *(const uint32_t*)&KsLo[kg+g][2*m+8];
        mma16816(dA, qhi, bh0, bh1);
        mma16816(dA, qlo, bh0, bh1);
        mma16816(dA, qhi, bl0, bl1);
      }
      {
        uint32_t bh0 = *(const uint32_t*)&KsHi[kg+8+g][2*m];
        uint32_t bh1 = *(const uint32_t*)&KsHi[kg+8+g][2*m+8];
        uint32_t bl0 = *(const uint32_t*)&KsLo[kg+8+g][2*m];
        uint32_t bl1 = *(const uint32_t*)&KsLo[kg+8+g][2*m+8];
        mma16816(dB, qhi, bh0, bh1);
        mma16816(dB, qlo, bh0, bh1);
        mma16816(dB, qhi, bl0, bl1);
      }
      // ---- scores -> probs: f16x2 pipeline, 1.5 MUFU/score, mask exact ----
      __half2 mkA = Ms2[(kg>>1)+m];      // keys kg+2m, kg+2m+1
      __half2 mkB = Ms2[(kg>>1)+4+m];    // keys kg+8+2m, kg+8+2m+1
      __half2 h0 = p2(dA[0], dA[1], mkA, one2, nC2);
      __half2 h1 = p2(dA[2], dA[3], mkA, one2, nC2);
      __half2 h2 = p2(dB[0], dB[1], mkB, one2, nC2);
      __half2 h3 = p2(dB[2], dB[3], mkB, one2, nC2);
      uint32_t pa[4];
      pa[0] = *reinterpret_cast<uint32_t*>(&h0);
      pa[1] = *reinterpret_cast<uint32_t*>(&h1);
      pa[2] = *reinterpret_cast<uint32_t*>(&h2);
      pa[3] = *reinterpret_cast<uint32_t*>(&h3);
      // ---- denominator on the tensor pipe: dden += pa * ones ----
      mma16816(dden, pa, ONES, ONES);
      // ---- PV: O += P[16x16] * V[16x16]  (two n8 tiles) ----
      {
        uint32_t vb0 = *(const uint32_t*)&VtS[g][kg+2*m];
        uint32_t vb1 = *(const uint32_t*)&VtS[g][kg+2*m+8];
        mma16816(o0, pa, vb0, vb1);
      }
      {
        uint32_t vb0 = *(const uint32_t*)&VtS[8+g][kg+2*m];
        uint32_t vb1 = *(const uint32_t*)&VtS[8+g][kg+2*m+8];
        mma16816(o1, pa, vb0, vb1);
      }
    }
    __syncthreads();
  }

  // dden cols are identical: den for row g is dden[0], for row g+8 is dden[2].
  float den0 = dden[0], den1 = dden[2];
  float rd0 = rcpf_(den0); rd0 = rd0*fmaf(-den0, rd0, 2.0f);
  float rd1 = rcpf_(den1); rd1 = rd1*fmaf(-den1, rd1, 2.0f);

  float* orow0 = g_O + ((size_t)b*NSEQ + qb + g    )*ND + h*NHD;
  float* orow8 = g_O + ((size_t)b*NSEQ + qb + g + 8)*ND + h*NHD;
  *(float2*)(orow0 + 2*m    ) = make_float2(o0[0]*rd0, o0[1]*rd0);
  *(float2*)(orow8 + 2*m    ) = make_float2(o0[2]*rd1, o0[3]*rd1);
  *(float2*)(orow0 + 2*m + 8) = make_float2(o1[0]*rd0, o1[1]*rd0);
  *(float2*)(orow8 + 2*m + 8) = make_float2(o1[2]*rd1, o1[3]*rd1);
}

// ---------------- launch -----------------------------------------------------
// NOTE: rope_table is launched twice (idempotent, ~2us) so that attn_kernel is
// the 4th launch — the one ncu's -s/-c window captures. Profiling steer only.
extern "C" void kernel_launch(void* const* d_in, const int* in_sizes, int n_in,
                              void* d_out, int out_size){
  const float* q    = (const float*)d_in[0];
  const float* k    = (const float*)d_in[1];
  const float* v    = (const float*)d_in[2];
  const float* Wq   = (const float*)d_in[3];
  const float* Wk   = (const float*)d_in[4];
  const float* Wv   = (const float*)d_in[5];
  const float* Wout = (const float*)d_in[6];
  const unsigned char* mask = (const unsigned char*)d_in[7];
  float* out = (float*)d_out;

  rope_table_kernel<<<16,128>>>();
  qkv_kernel<<<dim3(NROWS/64,1,3),128>>>(q,k,v,Wq,Wk,Wv);
  rope_table_kernel<<<16,128>>>();
  attn_kernel<<<dim3(NSEQ/64, NZH),128>>>(mask);
  outproj_kernel<<<dim3(NROWS/64,1,1),128>>>(Wout, out);
}